// round 2
// baseline (speedup 1.0000x reference)
#include <cuda_runtime.h>

#define B_ 4
#define C_ 64
#define N_ 100000
#define K_ 6
#define BN_ (B_ * N_)
#define EPS_ 1e-5f

// Scratch (device-global per the allocation rules)
__device__ float g_xt[(size_t)BN_ * C_];   // x transposed to [B*N, 64]
__device__ float g_h[(size_t)BN_ * C_];    // conv1 output (pre-relu), [B*N, 64]
__device__ float g_W0t[128 * 64];          // W0 as [k(=s*64+c)][o]
__device__ float g_W1t[128 * 64];
__device__ float g_sum[C_];
__device__ float g_ssq[C_];
__device__ float g_a[C_];                  // gamma * rstd
__device__ float g_bc[C_];                 // beta - mean * gamma * rstd

// ---------------------------------------------------------------------------
// prep: zero stats, transpose W0/W1 from [O][C][S] to [S*64+C][O]
// ---------------------------------------------------------------------------
__global__ void prep_k(const float* __restrict__ W0, const float* __restrict__ W1) {
    int t = threadIdx.x;
    if (t < 64) { g_sum[t] = 0.f; g_ssq[t] = 0.f; }
    for (int d = t; d < 8192; d += 256) {
        int k = d >> 6, o = d & 63;
        int c = k & 63, s = k >> 6;
        int src = o * 128 + c * 2 + s;
        g_W0t[d] = W0[src];
        g_W1t[d] = W1[src];
    }
}

// ---------------------------------------------------------------------------
// transpose x [B][C][N] -> g_xt [B*N][C]
// ---------------------------------------------------------------------------
__global__ void transpose_k(const float* __restrict__ x) {
    __shared__ float tile[64][33];
    int b = blockIdx.y;
    int n0 = blockIdx.x * 32;
    const float* xb = x + (size_t)b * C_ * N_;
    int t = threadIdx.x;
#pragma unroll
    for (int i = 0; i < 8; i++) {
        int idx = t + i * 256;
        int c = idx >> 5, j = idx & 31;
        tile[c][j] = xb[(size_t)c * N_ + n0 + j];
    }
    __syncthreads();
    float* dst = g_xt + ((size_t)b * N_ + n0) * C_;
#pragma unroll
    for (int i = 0; i < 8; i++) {
        int idx = t + i * 256;
        int j = idx >> 6, c = idx & 63;
        dst[j * C_ + c] = tile[c][j];
    }
}

// ---------------------------------------------------------------------------
// conv1: per 32-vertex tile — gather (center + 6-neighbor sum) -> G[128][32],
// GEMM vs smem W (each thread: 8 outputs for 1 vertex), store h, accumulate
// relu stats.
// ---------------------------------------------------------------------------
__global__ __launch_bounds__(256) void conv1_k(const int* __restrict__ neigh) {
    __shared__ float Ws[128][64];   // 32 KB
    __shared__ float G[128][32];    // 16 KB  (total = 48 KB exactly)

    int b  = blockIdx.y;
    int n0 = blockIdx.x * 32;
    int tid = threadIdx.x;
    int v = tid & 31, cg = tid >> 5;

    for (int i = tid; i < 8192; i += 256)
        (&Ws[0][0])[i] = g_W0t[i];

    int n = n0 + v;
    int rbase = b * N_;
    const float4* xt4 = (const float4*)g_xt;
    const int* nb = neigh + ((size_t)rbase + n) * K_;
    int idxs[6];
#pragma unroll
    for (int k = 0; k < 6; k++) idxs[k] = nb[k];

    size_t crow = (size_t)(rbase + n) * 16 + cg * 2;
    float4 c0 = xt4[crow], c1 = xt4[crow + 1];
    float4 s0 = make_float4(0.f, 0.f, 0.f, 0.f);
    float4 s1 = make_float4(0.f, 0.f, 0.f, 0.f);
#pragma unroll
    for (int k = 0; k < 6; k++) {
        size_t r = (size_t)(rbase + idxs[k]) * 16 + cg * 2;
        float4 a0 = xt4[r], a1 = xt4[r + 1];
        s0.x += a0.x; s0.y += a0.y; s0.z += a0.z; s0.w += a0.w;
        s1.x += a1.x; s1.y += a1.y; s1.z += a1.z; s1.w += a1.w;
    }
    int cbase = cg * 8;
    G[cbase + 0][v] = c0.x; G[cbase + 1][v] = c0.y; G[cbase + 2][v] = c0.z; G[cbase + 3][v] = c0.w;
    G[cbase + 4][v] = c1.x; G[cbase + 5][v] = c1.y; G[cbase + 6][v] = c1.z; G[cbase + 7][v] = c1.w;
    G[64 + cbase + 0][v] = s0.x; G[64 + cbase + 1][v] = s0.y; G[64 + cbase + 2][v] = s0.z; G[64 + cbase + 3][v] = s0.w;
    G[64 + cbase + 4][v] = s1.x; G[64 + cbase + 5][v] = s1.y; G[64 + cbase + 6][v] = s1.z; G[64 + cbase + 7][v] = s1.w;
    __syncthreads();

    float acc[8];
#pragma unroll
    for (int i = 0; i < 8; i++) acc[i] = 0.f;
#pragma unroll 8
    for (int k = 0; k < 128; k++) {
        float g = G[k][v];
        float4 w0 = ((const float4*)Ws[k])[cg * 2];
        float4 w1 = ((const float4*)Ws[k])[cg * 2 + 1];
        acc[0] += g * w0.x; acc[1] += g * w0.y; acc[2] += g * w0.z; acc[3] += g * w0.w;
        acc[4] += g * w1.x; acc[5] += g * w1.y; acc[6] += g * w1.z; acc[7] += g * w1.w;
    }

    float4* h4 = (float4*)g_h;
    h4[crow]     = make_float4(acc[0], acc[1], acc[2], acc[3]);
    h4[crow + 1] = make_float4(acc[4], acc[5], acc[6], acc[7]);

    // relu stats: this warp owns channels cbase..cbase+7 exclusively in block
#pragma unroll
    for (int i = 0; i < 8; i++) {
        float s = fmaxf(acc[i], 0.f);
        float q = s * s;
#pragma unroll
        for (int off = 16; off; off >>= 1) {
            s += __shfl_xor_sync(0xffffffffu, s, off);
            q += __shfl_xor_sync(0xffffffffu, q, off);
        }
        if (v == 0) {
            atomicAdd(&g_sum[cbase + i], s);
            atomicAdd(&g_ssq[cbase + i], q);
        }
    }
}

// ---------------------------------------------------------------------------
// BN finalize: fold stats + gamma/beta into per-channel affine (a, b)
// ---------------------------------------------------------------------------
__global__ void finalize_k(const float* __restrict__ gamma, const float* __restrict__ beta) {
    int c = threadIdx.x;
    float inv = 1.f / (float)BN_;
    float mean = g_sum[c] * inv;
    float var  = g_ssq[c] * inv - mean * mean;
    float a = gamma[c] * rsqrtf(var + EPS_);
    g_a[c]  = a;
    g_bc[c] = beta[c] - mean * a;
}

// ---------------------------------------------------------------------------
// conv2: gather raw h, features = a*relu(h)+b (center) and a*Σrelu(h_k)+6b
// (neighbors); GEMM vs W1; + residual h; relu; write [B][C][N] output.
// ---------------------------------------------------------------------------
__global__ __launch_bounds__(256) void conv2_k(const int* __restrict__ neigh,
                                               float* __restrict__ out) {
    __shared__ float Ws[128][64];
    __shared__ float G[128][32];

    int b  = blockIdx.y;
    int n0 = blockIdx.x * 32;
    int tid = threadIdx.x;
    int v = tid & 31, cg = tid >> 5;
    int cbase = cg * 8;

    for (int i = tid; i < 8192; i += 256)
        (&Ws[0][0])[i] = g_W1t[i];

    float av[8], bv[8];
#pragma unroll
    for (int i = 0; i < 8; i++) { av[i] = g_a[cbase + i]; bv[i] = g_bc[cbase + i]; }

    int n = n0 + v;
    int rbase = b * N_;
    const float4* h4 = (const float4*)g_h;
    const int* nb = neigh + ((size_t)rbase + n) * K_;
    int idxs[6];
#pragma unroll
    for (int k = 0; k < 6; k++) idxs[k] = nb[k];

    size_t crow = (size_t)(rbase + n) * 16 + cg * 2;
    float4 hc0 = h4[crow], hc1 = h4[crow + 1];
    float4 s0 = make_float4(0.f, 0.f, 0.f, 0.f);
    float4 s1 = make_float4(0.f, 0.f, 0.f, 0.f);
#pragma unroll
    for (int k = 0; k < 6; k++) {
        size_t r = (size_t)(rbase + idxs[k]) * 16 + cg * 2;
        float4 a0 = h4[r], a1 = h4[r + 1];
        s0.x += fmaxf(a0.x, 0.f); s0.y += fmaxf(a0.y, 0.f);
        s0.z += fmaxf(a0.z, 0.f); s0.w += fmaxf(a0.w, 0.f);
        s1.x += fmaxf(a1.x, 0.f); s1.y += fmaxf(a1.y, 0.f);
        s1.z += fmaxf(a1.z, 0.f); s1.w += fmaxf(a1.w, 0.f);
    }
    // center: a*relu(h)+b
    G[cbase + 0][v] = av[0] * fmaxf(hc0.x, 0.f) + bv[0];
    G[cbase + 1][v] = av[1] * fmaxf(hc0.y, 0.f) + bv[1];
    G[cbase + 2][v] = av[2] * fmaxf(hc0.z, 0.f) + bv[2];
    G[cbase + 3][v] = av[3] * fmaxf(hc0.w, 0.f) + bv[3];
    G[cbase + 4][v] = av[4] * fmaxf(hc1.x, 0.f) + bv[4];
    G[cbase + 5][v] = av[5] * fmaxf(hc1.y, 0.f) + bv[5];
    G[cbase + 6][v] = av[6] * fmaxf(hc1.z, 0.f) + bv[6];
    G[cbase + 7][v] = av[7] * fmaxf(hc1.w, 0.f) + bv[7];
    // neighbor sum: a*Σrelu + K*b
    G[64 + cbase + 0][v] = av[0] * s0.x + 6.f * bv[0];
    G[64 + cbase + 1][v] = av[1] * s0.y + 6.f * bv[1];
    G[64 + cbase + 2][v] = av[2] * s0.z + 6.f * bv[2];
    G[64 + cbase + 3][v] = av[3] * s0.w + 6.f * bv[3];
    G[64 + cbase + 4][v] = av[4] * s1.x + 6.f * bv[4];
    G[64 + cbase + 5][v] = av[5] * s1.y + 6.f * bv[5];
    G[64 + cbase + 6][v] = av[6] * s1.z + 6.f * bv[6];
    G[64 + cbase + 7][v] = av[7] * s1.w + 6.f * bv[7];
    __syncthreads();

    float acc[8];
#pragma unroll
    for (int i = 0; i < 8; i++) acc[i] = 0.f;
#pragma unroll 8
    for (int k = 0; k < 128; k++) {
        float g = G[k][v];
        float4 w0 = ((const float4*)Ws[k])[cg * 2];
        float4 w1 = ((const float4*)Ws[k])[cg * 2 + 1];
        acc[0] += g * w0.x; acc[1] += g * w0.y; acc[2] += g * w0.z; acc[3] += g * w0.w;
        acc[4] += g * w1.x; acc[5] += g * w1.y; acc[6] += g * w1.z; acc[7] += g * w1.w;
    }

    float res[8] = {hc0.x, hc0.y, hc0.z, hc0.w, hc1.x, hc1.y, hc1.z, hc1.w};
#pragma unroll
    for (int i = 0; i < 8; i++) {
        float oval = fmaxf(acc[i] + res[i], 0.f);
        out[((size_t)(b * 64 + cbase + i)) * N_ + n] = oval;
    }
}

// ---------------------------------------------------------------------------
extern "C" void kernel_launch(void* const* d_in, const int* in_sizes, int n_in,
                              void* d_out, int out_size) {
    const float* x     = (const float*)d_in[0];
    const int*   neigh = (const int*)d_in[1];
    const float* W0    = (const float*)d_in[2];
    const float* W1    = (const float*)d_in[3];
    const float* gamma = (const float*)d_in[4];
    const float* beta  = (const float*)d_in[5];
    float* out = (float*)d_out;

    dim3 grid(N_ / 32, B_);
    prep_k<<<1, 256>>>(W0, W1);
    transpose_k<<<grid, 256>>>(x);
    conv1_k<<<grid, 256>>>(neigh);
    finalize_k<<<1, 64>>>(gamma, beta);
    conv2_k<<<grid, 256>>>(neigh, out);
}

// round 5
// speedup vs baseline: 1.2939x; 1.2939x over previous
#include <cuda_runtime.h>

#define B_ 4
#define C_ 64
#define N_ 100000
#define K_ 6
#define BN_ (B_ * N_)
#define EPS_ 1e-5f
#define TILE_V 64
#define NTILES ((N_ + TILE_V - 1) / TILE_V)   // 1563
#define SMEM_BYTES 98304                      // Wd 64KB + G 32KB

// Scratch (device globals per allocation rules)
__device__ float g_xt[(size_t)BN_ * C_];   // x transposed to [B*N, 64]
__device__ float g_h[(size_t)BN_ * C_];    // conv1 output (pre-relu), [B*N, 64]
__device__ float g_Wd0[128 * 128];         // W0 dup'd: [k][2o]=[k][2o+1]=w[o][k]
__device__ float g_Wd1[128 * 128];
__device__ float g_sum[C_];
__device__ float g_ssq[C_];
__device__ float g_a[C_];                  // gamma * rstd
__device__ float g_bc[C_];                 // beta - mean * gamma * rstd

__device__ __forceinline__ void ffma2(unsigned long long& d,
                                      unsigned long long a,
                                      unsigned long long b) {
    asm("fma.rn.f32x2 %0, %1, %2, %0;" : "+l"(d) : "l"(a), "l"(b));
}
__device__ __forceinline__ float2 u2f(unsigned long long v) {
    float2 f; asm("mov.b64 {%0,%1}, %2;" : "=f"(f.x), "=f"(f.y) : "l"(v)); return f;
}

// ---------------------------------------------------------------------------
// prep: zero stats; build duplicated weights Wd[k][2o]=Wd[k][2o+1]=W[o][c][s],
// k = s*64 + c
// ---------------------------------------------------------------------------
__global__ void prep_k(const float* __restrict__ W0, const float* __restrict__ W1) {
    int t = threadIdx.x;
    if (t < 64) { g_sum[t] = 0.f; g_ssq[t] = 0.f; }
    for (int d = t; d < 16384; d += 256) {
        int k = d >> 7, oo = d & 127, o = oo >> 1;
        int c = k & 63, s = k >> 6;
        int src = o * 128 + c * 2 + s;
        g_Wd0[d] = W0[src];
        g_Wd1[d] = W1[src];
    }
}

// ---------------------------------------------------------------------------
// transpose x [B][C][N] -> g_xt [B*N][C]
// ---------------------------------------------------------------------------
__global__ void transpose_k(const float* __restrict__ x) {
    __shared__ float tile[64][33];
    int b = blockIdx.y;
    int n0 = blockIdx.x * 32;
    const float* xb = x + (size_t)b * C_ * N_;
    int t = threadIdx.x;
#pragma unroll
    for (int i = 0; i < 8; i++) {
        int idx = t + i * 256;
        int c = idx >> 5, j = idx & 31;
        tile[c][j] = xb[(size_t)c * N_ + n0 + j];
    }
    __syncthreads();
    float* dst = g_xt + ((size_t)b * N_ + n0) * C_;
#pragma unroll
    for (int i = 0; i < 8; i++) {
        int idx = t + i * 256;
        int j = idx >> 6, c = idx & 63;
        dst[j * C_ + c] = tile[c][j];
    }
}

// ---------------------------------------------------------------------------
// conv1: gather center + 6-neighbor-sum into G[128][64], FFMA2 GEMM vs dup'd
// W in smem (thread = 4 vertices x 8 outputs), store h, accumulate relu stats.
// ---------------------------------------------------------------------------
__global__ __launch_bounds__(128) void conv1_k(const int* __restrict__ neigh) {
    extern __shared__ float smem[];
    float* Wd = smem;           // 128*128
    float* G  = smem + 16384;   // 128*64

    int b   = blockIdx.y;
    int n0  = blockIdx.x * TILE_V;
    int tid = threadIdx.x;
    int rbase = b * N_;

    {   // stage dup'd weights
        const float4* src = (const float4*)g_Wd0;
        float4* dst = (float4*)Wd;
        for (int i = tid; i < 4096; i += 128) dst[i] = src[i];
    }

    {   // gather phase: thread = (vertex v, channel-half)
        int v = tid & 63, half = tid >> 6;
        int n = n0 + v;
        bool ok = (n < N_);
        const float4* xt4 = (const float4*)g_xt;
        int idxs[6];
        if (ok) {
            const int* nb = neigh + (size_t)(rbase + n) * K_;
#pragma unroll
            for (int k = 0; k < 6; k++) idxs[k] = nb[k];
        }
        size_t crow = (size_t)(rbase + n) * 16 + half * 8;
#pragma unroll
        for (int ch = 0; ch < 2; ch++) {
            float4 cen[4], sm[4];
#pragma unroll
            for (int j = 0; j < 4; j++) {
                cen[j] = make_float4(0.f, 0.f, 0.f, 0.f);
                sm[j]  = make_float4(0.f, 0.f, 0.f, 0.f);
            }
            if (ok) {
#pragma unroll
                for (int j = 0; j < 4; j++) cen[j] = xt4[crow + ch * 4 + j];
#pragma unroll
                for (int k = 0; k < 6; k++) {
                    size_t r = (size_t)(rbase + idxs[k]) * 16 + half * 8 + ch * 4;
#pragma unroll
                    for (int j = 0; j < 4; j++) {
                        float4 a = xt4[r + j];
                        sm[j].x += a.x; sm[j].y += a.y; sm[j].z += a.z; sm[j].w += a.w;
                    }
                }
            }
            int cb = half * 32 + ch * 16;
#pragma unroll
            for (int j = 0; j < 4; j++) {
                int c = cb + j * 4;
                G[(c + 0) * 64 + v] = cen[j].x;
                G[(c + 1) * 64 + v] = cen[j].y;
                G[(c + 2) * 64 + v] = cen[j].z;
                G[(c + 3) * 64 + v] = cen[j].w;
                G[(64 + c + 0) * 64 + v] = sm[j].x;
                G[(64 + c + 1) * 64 + v] = sm[j].y;
                G[(64 + c + 2) * 64 + v] = sm[j].z;
                G[(64 + c + 3) * 64 + v] = sm[j].w;
            }
        }
    }
    __syncthreads();

    // GEMM: thread = (vg: 4 vertices, og: 8 outputs)
    int vg = tid & 15, og = tid >> 4;
    unsigned long long acc[8][2];
#pragma unroll
    for (int o = 0; o < 8; o++) { acc[o][0] = 0ull; acc[o][1] = 0ull; }

    const float* Gp = G + 4 * vg;
    const float* Wp = Wd + og * 16;
#pragma unroll 16
    for (int k = 0; k < 128; k++) {
        ulonglong2 g = *(const ulonglong2*)(Gp + k * 64);
        const ulonglong2* wv = (const ulonglong2*)(Wp + k * 128);
        ulonglong2 wa = wv[0], wb = wv[1], wc = wv[2], we = wv[3];
        ffma2(acc[0][0], g.x, wa.x); ffma2(acc[0][1], g.y, wa.x);
        ffma2(acc[1][0], g.x, wa.y); ffma2(acc[1][1], g.y, wa.y);
        ffma2(acc[2][0], g.x, wb.x); ffma2(acc[2][1], g.y, wb.x);
        ffma2(acc[3][0], g.x, wb.y); ffma2(acc[3][1], g.y, wb.y);
        ffma2(acc[4][0], g.x, wc.x); ffma2(acc[4][1], g.y, wc.x);
        ffma2(acc[5][0], g.x, wc.y); ffma2(acc[5][1], g.y, wc.y);
        ffma2(acc[6][0], g.x, we.x); ffma2(acc[6][1], g.y, we.x);
        ffma2(acc[7][0], g.x, we.y); ffma2(acc[7][1], g.y, we.y);
    }

    // unpack: av[vertex i][output o]
    float av[4][8];
#pragma unroll
    for (int o = 0; o < 8; o++) {
        float2 p0 = u2f(acc[o][0]), p1 = u2f(acc[o][1]);
        av[0][o] = p0.x; av[1][o] = p0.y; av[2][o] = p1.x; av[3][o] = p1.y;
    }

    float4* h4 = (float4*)g_h;
#pragma unroll
    for (int i = 0; i < 4; i++) {
        int n = n0 + 4 * vg + i;
        if (n < N_) {
            size_t row = (size_t)(rbase + n) * 16 + og * 2;
            h4[row]     = make_float4(av[i][0], av[i][1], av[i][2], av[i][3]);
            h4[row + 1] = make_float4(av[i][4], av[i][5], av[i][6], av[i][7]);
        }
    }

    // relu stats (invalid vertices have G cols zeroed -> acc 0 -> contribute 0)
#pragma unroll
    for (int o = 0; o < 8; o++) {
        float s = 0.f, q = 0.f;
#pragma unroll
        for (int i = 0; i < 4; i++) {
            float r = fmaxf(av[i][o], 0.f);
            s += r; q += r * r;
        }
#pragma unroll
        for (int off = 8; off; off >>= 1) {
            s += __shfl_xor_sync(0xffffffffu, s, off);
            q += __shfl_xor_sync(0xffffffffu, q, off);
        }
        if ((tid & 15) == 0) {
            atomicAdd(&g_sum[og * 8 + o], s);
            atomicAdd(&g_ssq[og * 8 + o], q);
        }
    }
}

// ---------------------------------------------------------------------------
// BN finalize: fold stats + gamma/beta into per-channel affine (a, b)
// ---------------------------------------------------------------------------
__global__ void finalize_k(const float* __restrict__ gamma, const float* __restrict__ beta) {
    int c = threadIdx.x;
    float inv = 1.f / (float)BN_;
    float mean = g_sum[c] * inv;
    float var  = g_ssq[c] * inv - mean * mean;
    float a = gamma[c] * rsqrtf(var + EPS_);
    g_a[c]  = a;
    g_bc[c] = beta[c] - mean * a;
}

// ---------------------------------------------------------------------------
// conv2: gather raw h, BN-affine folded into features; FFMA2 GEMM; +residual;
// relu; write [B][C][N] output with vertex-quad float4 stores.
// ---------------------------------------------------------------------------
__global__ __launch_bounds__(128) void conv2_k(const int* __restrict__ neigh,
                                               float* __restrict__ out) {
    extern __shared__ float smem[];
    float* Wd = smem;
    float* G  = smem + 16384;

    int b   = blockIdx.y;
    int n0  = blockIdx.x * TILE_V;
    int tid = threadIdx.x;
    int rbase = b * N_;

    {
        const float4* src = (const float4*)g_Wd1;
        float4* dst = (float4*)Wd;
        for (int i = tid; i < 4096; i += 128) dst[i] = src[i];
    }

    {   // gather: center a*relu(h)+b ; neighbors a*sum(relu(h_k)) + 6b
        int v = tid & 63, half = tid >> 6;
        int n = n0 + v;
        bool ok = (n < N_);
        const float4* h4 = (const float4*)g_h;
        const float4* a4 = (const float4*)g_a;
        const float4* b4 = (const float4*)g_bc;
        int idxs[6];
        if (ok) {
            const int* nb = neigh + (size_t)(rbase + n) * K_;
#pragma unroll
            for (int k = 0; k < 6; k++) idxs[k] = nb[k];
        }
        size_t crow = (size_t)(rbase + n) * 16 + half * 8;
#pragma unroll
        for (int ch = 0; ch < 2; ch++) {
            float4 cen[4], sm[4];
#pragma unroll
            for (int j = 0; j < 4; j++) {
                cen[j] = make_float4(0.f, 0.f, 0.f, 0.f);
                sm[j]  = make_float4(0.f, 0.f, 0.f, 0.f);
            }
            if (ok) {
#pragma unroll
                for (int j = 0; j < 4; j++) cen[j] = h4[crow + ch * 4 + j];
#pragma unroll
                for (int k = 0; k < 6; k++) {
                    size_t r = (size_t)(rbase + idxs[k]) * 16 + half * 8 + ch * 4;
#pragma unroll
                    for (int j = 0; j < 4; j++) {
                        float4 a = h4[r + j];
                        sm[j].x += fmaxf(a.x, 0.f); sm[j].y += fmaxf(a.y, 0.f);
                        sm[j].z += fmaxf(a.z, 0.f); sm[j].w += fmaxf(a.w, 0.f);
                    }
                }
            }
            int cb = half * 32 + ch * 16;
#pragma unroll
            for (int j = 0; j < 4; j++) {
                int c = cb + j * 4;
                float4 aa = a4[(c) >> 2];
                float4 bb = b4[(c) >> 2];
                G[(c + 0) * 64 + v] = aa.x * fmaxf(cen[j].x, 0.f) + bb.x;
                G[(c + 1) * 64 + v] = aa.y * fmaxf(cen[j].y, 0.f) + bb.y;
                G[(c + 2) * 64 + v] = aa.z * fmaxf(cen[j].z, 0.f) + bb.z;
                G[(c + 3) * 64 + v] = aa.w * fmaxf(cen[j].w, 0.f) + bb.w;
                G[(64 + c + 0) * 64 + v] = aa.x * sm[j].x + 6.f * bb.x;
                G[(64 + c + 1) * 64 + v] = aa.y * sm[j].y + 6.f * bb.y;
                G[(64 + c + 2) * 64 + v] = aa.z * sm[j].z + 6.f * bb.z;
                G[(64 + c + 3) * 64 + v] = aa.w * sm[j].w + 6.f * bb.w;
            }
        }
    }
    __syncthreads();

    int vg = tid & 15, og = tid >> 4;
    unsigned long long acc[8][2];
#pragma unroll
    for (int o = 0; o < 8; o++) { acc[o][0] = 0ull; acc[o][1] = 0ull; }

    const float* Gp = G + 4 * vg;
    const float* Wp = Wd + og * 16;
#pragma unroll 16
    for (int k = 0; k < 128; k++) {
        ulonglong2 g = *(const ulonglong2*)(Gp + k * 64);
        const ulonglong2* wv = (const ulonglong2*)(Wp + k * 128);
        ulonglong2 wa = wv[0], wb = wv[1], wc = wv[2], we = wv[3];
        ffma2(acc[0][0], g.x, wa.x); ffma2(acc[0][1], g.y, wa.x);
        ffma2(acc[1][0], g.x, wa.y); ffma2(acc[1][1], g.y, wa.y);
        ffma2(acc[2][0], g.x, wb.x); ffma2(acc[2][1], g.y, wb.x);
        ffma2(acc[3][0], g.x, wb.y); ffma2(acc[3][1], g.y, wb.y);
        ffma2(acc[4][0], g.x, wc.x); ffma2(acc[4][1], g.y, wc.x);
        ffma2(acc[5][0], g.x, wc.y); ffma2(acc[5][1], g.y, wc.y);
        ffma2(acc[6][0], g.x, we.x); ffma2(acc[6][1], g.y, we.x);
        ffma2(acc[7][0], g.x, we.y); ffma2(acc[7][1], g.y, we.y);
    }

    float av[4][8];
#pragma unroll
    for (int o = 0; o < 8; o++) {
        float2 p0 = u2f(acc[o][0]), p1 = u2f(acc[o][1]);
        av[0][o] = p0.x; av[1][o] = p0.y; av[2][o] = p1.x; av[3][o] = p1.y;
    }

    // residual + relu, then transposed float4 stores (4 consecutive vertices)
    int nq = n0 + 4 * vg;
    if (nq < N_) {
        const float4* h4 = (const float4*)g_h;
#pragma unroll
        for (int i = 0; i < 4; i++) {
            size_t row = (size_t)(rbase + nq + i) * 16 + og * 2;
            float4 r0 = h4[row], r1 = h4[row + 1];
            av[i][0] = fmaxf(av[i][0] + r0.x, 0.f);
            av[i][1] = fmaxf(av[i][1] + r0.y, 0.f);
            av[i][2] = fmaxf(av[i][2] + r0.z, 0.f);
            av[i][3] = fmaxf(av[i][3] + r0.w, 0.f);
            av[i][4] = fmaxf(av[i][4] + r1.x, 0.f);
            av[i][5] = fmaxf(av[i][5] + r1.y, 0.f);
            av[i][6] = fmaxf(av[i][6] + r1.z, 0.f);
            av[i][7] = fmaxf(av[i][7] + r1.w, 0.f);
        }
#pragma unroll
        for (int o = 0; o < 8; o++) {
            float4 v4 = make_float4(av[0][o], av[1][o], av[2][o], av[3][o]);
            *(float4*)(out + (size_t)(b * 64 + og * 8 + o) * N_ + nq) = v4;
        }
    }
}

// ---------------------------------------------------------------------------
extern "C" void kernel_launch(void* const* d_in, const int* in_sizes, int n_in,
                              void* d_out, int out_size) {
    const float* x     = (const float*)d_in[0];
    const int*   neigh = (const int*)d_in[1];
    const float* W0    = (const float*)d_in[2];
    const float* W1    = (const float*)d_in[3];
    const float* gamma = (const float*)d_in[4];
    const float* beta  = (const float*)d_in[5];
    float* out = (float*)d_out;

    cudaFuncSetAttribute(conv1_k, cudaFuncAttributeMaxDynamicSharedMemorySize, SMEM_BYTES);
    cudaFuncSetAttribute(conv2_k, cudaFuncAttributeMaxDynamicSharedMemorySize, SMEM_BYTES);

    dim3 gtr(N_ / 32, B_);
    dim3 gconv(NTILES, B_);
    prep_k<<<1, 256>>>(W0, W1);
    transpose_k<<<gtr, 256>>>(x);
    conv1_k<<<gconv, 128, SMEM_BYTES>>>(neigh);
    finalize_k<<<1, 64>>>(gamma, beta);
    conv2_k<<<gconv, 128, SMEM_BYTES>>>(neigh, out);
}

// round 7
// speedup vs baseline: 1.4957x; 1.1559x over previous
#include <cuda_runtime.h>

#define B_ 4
#define C_ 64
#define N_ 100000
#define K_ 6
#define BN_ (B_ * N_)
#define EPS_ 1e-5f
#define TILE_V 64
#define NTILES ((N_ + TILE_V - 1) / TILE_V)   // 1563
#define SMEM_BYTES 65536                      // Ws 32KB + G 32KB -> 3 CTAs/SM

// Scratch (device globals per allocation rules)
__device__ float g_xt[(size_t)BN_ * C_];   // x transposed to [B*N, 64]
__device__ float g_h[(size_t)BN_ * C_];    // conv1 output (pre-relu), [B*N, 64]
__device__ float g_W0t[128 * 64];          // W as [k(=s*64+c)][o] (non-duplicated)
__device__ float g_W1t[128 * 64];
__device__ float g_sum[C_];
__device__ float g_ssq[C_];
__device__ float g_a[C_];                  // gamma * rstd
__device__ float g_bc[C_];                 // beta - mean * gamma * rstd

__device__ __forceinline__ void ffma2(unsigned long long& d,
                                      unsigned long long a,
                                      unsigned long long b) {
    asm("fma.rn.f32x2 %0, %1, %2, %0;" : "+l"(d) : "l"(a), "l"(b));
}
__device__ __forceinline__ unsigned long long dup2(float g) {
    unsigned long long v;
    asm("mov.b64 %0, {%1, %1};" : "=l"(v) : "f"(g));
    return v;
}
__device__ __forceinline__ float2 u2f(unsigned long long v) {
    float2 f; asm("mov.b64 {%0,%1}, %2;" : "=f"(f.x), "=f"(f.y) : "l"(v)); return f;
}

// ---------------------------------------------------------------------------
// prep: zero stats, transpose W0/W1 from [O][C][S] to [S*64+C][O]
// ---------------------------------------------------------------------------
__global__ void prep_k(const float* __restrict__ W0, const float* __restrict__ W1) {
    int t = threadIdx.x;
    if (t < 64) { g_sum[t] = 0.f; g_ssq[t] = 0.f; }
    for (int d = t; d < 8192; d += 256) {
        int k = d >> 6, o = d & 63;
        int c = k & 63, s = k >> 6;
        int src = o * 128 + c * 2 + s;
        g_W0t[d] = W0[src];
        g_W1t[d] = W1[src];
    }
}

// ---------------------------------------------------------------------------
// transpose x [B][C][N] -> g_xt [B*N][C]
// ---------------------------------------------------------------------------
__global__ void transpose_k(const float* __restrict__ x) {
    __shared__ float tile[64][33];
    int b = blockIdx.y;
    int n0 = blockIdx.x * 32;
    const float* xb = x + (size_t)b * C_ * N_;
    int t = threadIdx.x;
#pragma unroll
    for (int i = 0; i < 8; i++) {
        int idx = t + i * 256;
        int c = idx >> 5, j = idx & 31;
        tile[c][j] = xb[(size_t)c * N_ + n0 + j];
    }
    __syncthreads();
    float* dst = g_xt + ((size_t)b * N_ + n0) * C_;
#pragma unroll
    for (int i = 0; i < 8; i++) {
        int idx = t + i * 256;
        int j = idx >> 6, c = idx & 63;
        dst[j * C_ + c] = tile[c][j];
    }
}

// ---------------------------------------------------------------------------
// GEMM inner loop: thread = 4 vertices x 8 outputs; f32x2 lanes = output pair.
// acc[v][p] accumulates outputs (og*8+2p, og*8+2p+1) for vertex 4*vg+v.
// ---------------------------------------------------------------------------
__device__ __forceinline__ void gemm_tile(const float* __restrict__ G,
                                          const float* __restrict__ Ws,
                                          int vg, int og,
                                          float av[4][8]) {
    unsigned long long acc[4][4];
#pragma unroll
    for (int v = 0; v < 4; v++)
#pragma unroll
        for (int p = 0; p < 4; p++) acc[v][p] = 0ull;

    const float* Gp = G + 4 * vg;
    const float* Wp = Ws + og * 8;
#pragma unroll 16
    for (int k = 0; k < 128; k++) {
        float4 g4 = *(const float4*)(Gp + (size_t)k * 64);
        ulonglong2 w01 = *(const ulonglong2*)(Wp + (size_t)k * 64);
        ulonglong2 w23 = *(const ulonglong2*)(Wp + (size_t)k * 64 + 4);
        unsigned long long gd0 = dup2(g4.x), gd1 = dup2(g4.y);
        unsigned long long gd2 = dup2(g4.z), gd3 = dup2(g4.w);
        ffma2(acc[0][0], gd0, w01.x); ffma2(acc[0][1], gd0, w01.y);
        ffma2(acc[0][2], gd0, w23.x); ffma2(acc[0][3], gd0, w23.y);
        ffma2(acc[1][0], gd1, w01.x); ffma2(acc[1][1], gd1, w01.y);
        ffma2(acc[1][2], gd1, w23.x); ffma2(acc[1][3], gd1, w23.y);
        ffma2(acc[2][0], gd2, w01.x); ffma2(acc[2][1], gd2, w01.y);
        ffma2(acc[2][2], gd2, w23.x); ffma2(acc[2][3], gd2, w23.y);
        ffma2(acc[3][0], gd3, w01.x); ffma2(acc[3][1], gd3, w01.y);
        ffma2(acc[3][2], gd3, w23.x); ffma2(acc[3][3], gd3, w23.y);
    }
#pragma unroll
    for (int v = 0; v < 4; v++)
#pragma unroll
        for (int p = 0; p < 4; p++) {
            float2 f = u2f(acc[v][p]);
            av[v][2 * p] = f.x;
            av[v][2 * p + 1] = f.y;
        }
}

// ---------------------------------------------------------------------------
// conv1: gather (center + 6-neighbor sum) -> G[128][64]; FFMA2 GEMM;
// store h; accumulate relu stats.
// ---------------------------------------------------------------------------
__global__ __launch_bounds__(128) void conv1_k(const int* __restrict__ neigh) {
    extern __shared__ float smem[];
    float* Ws = smem;           // 128*64
    float* G  = smem + 8192;    // 128*64

    int b   = blockIdx.y;
    int n0  = blockIdx.x * TILE_V;
    int tid = threadIdx.x;
    int rbase = b * N_;

    {   // stage weights (32 KB)
        const float4* src = (const float4*)g_W0t;
        float4* dst = (float4*)Ws;
        for (int i = tid; i < 2048; i += 128) dst[i] = src[i];
    }

    {   // gather phase: thread = (vertex v, channel-half)
        int v = tid & 63, half = tid >> 6;
        int n = n0 + v;
        bool ok = (n < N_);
        const float4* xt4 = (const float4*)g_xt;
        int idxs[6];
        if (ok) {
            const int* nb = neigh + (size_t)(rbase + n) * K_;
#pragma unroll
            for (int k = 0; k < 6; k++) idxs[k] = nb[k];
        }
        size_t crow = (size_t)(rbase + n) * 16 + half * 8;
#pragma unroll
        for (int ch = 0; ch < 2; ch++) {
            float4 cen[4], sm[4];
#pragma unroll
            for (int j = 0; j < 4; j++) {
                cen[j] = make_float4(0.f, 0.f, 0.f, 0.f);
                sm[j]  = make_float4(0.f, 0.f, 0.f, 0.f);
            }
            if (ok) {
#pragma unroll
                for (int j = 0; j < 4; j++) cen[j] = xt4[crow + ch * 4 + j];
#pragma unroll
                for (int k = 0; k < 6; k++) {
                    size_t r = (size_t)(rbase + idxs[k]) * 16 + half * 8 + ch * 4;
#pragma unroll
                    for (int j = 0; j < 4; j++) {
                        float4 a = xt4[r + j];
                        sm[j].x += a.x; sm[j].y += a.y; sm[j].z += a.z; sm[j].w += a.w;
                    }
                }
            }
            int cb = half * 32 + ch * 16;
#pragma unroll
            for (int j = 0; j < 4; j++) {
                int c = cb + j * 4;
                G[(c + 0) * 64 + v] = cen[j].x;
                G[(c + 1) * 64 + v] = cen[j].y;
                G[(c + 2) * 64 + v] = cen[j].z;
                G[(c + 3) * 64 + v] = cen[j].w;
                G[(64 + c + 0) * 64 + v] = sm[j].x;
                G[(64 + c + 1) * 64 + v] = sm[j].y;
                G[(64 + c + 2) * 64 + v] = sm[j].z;
                G[(64 + c + 3) * 64 + v] = sm[j].w;
            }
        }
    }
    __syncthreads();

    int vg = tid & 15, og = tid >> 4;
    float av[4][8];
    gemm_tile(G, Ws, vg, og, av);

    float4* h4 = (float4*)g_h;
#pragma unroll
    for (int i = 0; i < 4; i++) {
        int n = n0 + 4 * vg + i;
        if (n < N_) {
            size_t row = (size_t)(rbase + n) * 16 + og * 2;
            h4[row]     = make_float4(av[i][0], av[i][1], av[i][2], av[i][3]);
            h4[row + 1] = make_float4(av[i][4], av[i][5], av[i][6], av[i][7]);
        }
    }

    // relu stats (invalid vertices have zeroed G cols -> acc 0 -> contribute 0)
#pragma unroll
    for (int o = 0; o < 8; o++) {
        float s = 0.f, q = 0.f;
#pragma unroll
        for (int i = 0; i < 4; i++) {
            float r = fmaxf(av[i][o], 0.f);
            s += r; q += r * r;
        }
#pragma unroll
        for (int off = 8; off; off >>= 1) {
            s += __shfl_xor_sync(0xffffffffu, s, off);
            q += __shfl_xor_sync(0xffffffffu, q, off);
        }
        if ((tid & 15) == 0) {
            atomicAdd(&g_sum[og * 8 + o], s);
            atomicAdd(&g_ssq[og * 8 + o], q);
        }
    }
}

// ---------------------------------------------------------------------------
// BN finalize: fold stats + gamma/beta into per-channel affine (a, b)
// ---------------------------------------------------------------------------
__global__ void finalize_k(const float* __restrict__ gamma, const float* __restrict__ beta) {
    int c = threadIdx.x;
    float inv = 1.f / (float)BN_;
    float mean = g_sum[c] * inv;
    float var  = g_ssq[c] * inv - mean * mean;
    float a = gamma[c] * rsqrtf(var + EPS_);
    g_a[c]  = a;
    g_bc[c] = beta[c] - mean * a;
}

// ---------------------------------------------------------------------------
// conv2: gather raw h with BN-affine folding; FFMA2 GEMM; +residual; relu;
// transposed float4 output stores.
// ---------------------------------------------------------------------------
__global__ __launch_bounds__(128) void conv2_k(const int* __restrict__ neigh,
                                               float* __restrict__ out) {
    extern __shared__ float smem[];
    float* Ws = smem;
    float* G  = smem + 8192;

    int b   = blockIdx.y;
    int n0  = blockIdx.x * TILE_V;
    int tid = threadIdx.x;
    int rbase = b * N_;

    {
        const float4* src = (const float4*)g_W1t;
        float4* dst = (float4*)Ws;
        for (int i = tid; i < 2048; i += 128) dst[i] = src[i];
    }

    {   // gather: center a*relu(h)+b ; neighbors a*sum(relu(h_k)) + 6b
        int v = tid & 63, half = tid >> 6;
        int n = n0 + v;
        bool ok = (n < N_);
        const float4* h4 = (const float4*)g_h;
        const float4* a4 = (const float4*)g_a;
        const float4* b4 = (const float4*)g_bc;
        int idxs[6];
        if (ok) {
            const int* nb = neigh + (size_t)(rbase + n) * K_;
#pragma unroll
            for (int k = 0; k < 6; k++) idxs[k] = nb[k];
        }
        size_t crow = (size_t)(rbase + n) * 16 + half * 8;
#pragma unroll
        for (int ch = 0; ch < 2; ch++) {
            float4 cen[4], sm[4];
#pragma unroll
            for (int j = 0; j < 4; j++) {
                cen[j] = make_float4(0.f, 0.f, 0.f, 0.f);
                sm[j]  = make_float4(0.f, 0.f, 0.f, 0.f);
            }
            if (ok) {
#pragma unroll
                for (int j = 0; j < 4; j++) cen[j] = h4[crow + ch * 4 + j];
#pragma unroll
                for (int k = 0; k < 6; k++) {
                    size_t r = (size_t)(rbase + idxs[k]) * 16 + half * 8 + ch * 4;
#pragma unroll
                    for (int j = 0; j < 4; j++) {
                        float4 a = h4[r + j];
                        sm[j].x += fmaxf(a.x, 0.f); sm[j].y += fmaxf(a.y, 0.f);
                        sm[j].z += fmaxf(a.z, 0.f); sm[j].w += fmaxf(a.w, 0.f);
                    }
                }
            }
            int cb = half * 32 + ch * 16;
#pragma unroll
            for (int j = 0; j < 4; j++) {
                int c = cb + j * 4;
                float4 aa = a4[(c) >> 2];
                float4 bb = b4[(c) >> 2];
                G[(c + 0) * 64 + v] = aa.x * fmaxf(cen[j].x, 0.f) + bb.x;
                G[(c + 1) * 64 + v] = aa.y * fmaxf(cen[j].y, 0.f) + bb.y;
                G[(c + 2) * 64 + v] = aa.z * fmaxf(cen[j].z, 0.f) + bb.z;
                G[(c + 3) * 64 + v] = aa.w * fmaxf(cen[j].w, 0.f) + bb.w;
                G[(64 + c + 0) * 64 + v] = aa.x * sm[j].x + 6.f * bb.x;
                G[(64 + c + 1) * 64 + v] = aa.y * sm[j].y + 6.f * bb.y;
                G[(64 + c + 2) * 64 + v] = aa.z * sm[j].z + 6.f * bb.z;
                G[(64 + c + 3) * 64 + v] = aa.w * sm[j].w + 6.f * bb.w;
            }
        }
    }
    __syncthreads();

    int vg = tid & 15, og = tid >> 4;
    float av[4][8];
    gemm_tile(G, Ws, vg, og, av);

    // residual + relu, then transposed float4 stores (4 consecutive vertices)
    int nq = n0 + 4 * vg;
    if (nq < N_) {
        const float4* h4 = (const float4*)g_h;
#pragma unroll
        for (int i = 0; i < 4; i++) {
            size_t row = (size_t)(rbase + nq + i) * 16 + og * 2;
            float4 r0 = h4[row], r1 = h4[row + 1];
            av[i][0] = fmaxf(av[i][0] + r0.x, 0.f);
            av[i][1] = fmaxf(av[i][1] + r0.y, 0.f);
            av[i][2] = fmaxf(av[i][2] + r0.z, 0.f);
            av[i][3] = fmaxf(av[i][3] + r0.w, 0.f);
            av[i][4] = fmaxf(av[i][4] + r1.x, 0.f);
            av[i][5] = fmaxf(av[i][5] + r1.y, 0.f);
            av[i][6] = fmaxf(av[i][6] + r1.z, 0.f);
            av[i][7] = fmaxf(av[i][7] + r1.w, 0.f);
        }
#pragma unroll
        for (int o = 0; o < 8; o++) {
            float4 v4 = make_float4(av[0][o], av[1][o], av[2][o], av[3][o]);
            *(float4*)(out + (size_t)(b * 64 + og * 8 + o) * N_ + nq) = v4;
        }
    }
}

// ---------------------------------------------------------------------------
extern "C" void kernel_launch(void* const* d_in, const int* in_sizes, int n_in,
                              void* d_out, int out_size) {
    const float* x     = (const float*)d_in[0];
    const int*   neigh = (const int*)d_in[1];
    const float* W0    = (const float*)d_in[2];
    const float* W1    = (const float*)d_in[3];
    const float* gamma = (const float*)d_in[4];
    const float* beta  = (const float*)d_in[5];
    float* out = (float*)d_out;

    cudaFuncSetAttribute(conv1_k, cudaFuncAttributeMaxDynamicSharedMemorySize, SMEM_BYTES);
    cudaFuncSetAttribute(conv2_k, cudaFuncAttributeMaxDynamicSharedMemorySize, SMEM_BYTES);

    dim3 gtr(N_ / 32, B_);
    dim3 gconv(NTILES, B_);
    prep_k<<<1, 256>>>(W0, W1);
    transpose_k<<<gtr, 256>>>(x);
    conv1_k<<<gconv, 128, SMEM_BYTES>>>(neigh);
    finalize_k<<<1, 64>>>(gamma, beta);
    conv2_k<<<gconv, 128, SMEM_BYTES>>>(neigh, out);
}

// round 8
// speedup vs baseline: 1.5865x; 1.0607x over previous
#include <cuda_runtime.h>

#define B_ 4
#define C_ 64
#define N_ 100000
#define K_ 6
#define BN_ (B_ * N_)
#define EPS_ 1e-5f
#define TILE_V 128
#define NTILES ((N_ + TILE_V - 1) / TILE_V)   // 782
#define SMEM_BYTES 98304                      // Ws 32KB + G 64KB -> 2 CTAs/SM

// Scratch (device globals per allocation rules)
__device__ float g_xt[(size_t)BN_ * C_];   // x transposed to [B*N, 64]
__device__ float g_h[(size_t)BN_ * C_];    // conv1 output (pre-relu), [B*N, 64]
__device__ float g_W0t[128 * 64];          // W as [k(=s*64+c)][o]
__device__ float g_W1t[128 * 64];
__device__ float g_sum[C_];
__device__ float g_ssq[C_];
__device__ float g_a[C_];                  // gamma * rstd
__device__ float g_bc[C_];                 // beta - mean * gamma * rstd

__device__ __forceinline__ void ffma2(unsigned long long& d,
                                      unsigned long long a,
                                      unsigned long long b) {
    asm("fma.rn.f32x2 %0, %1, %2, %0;" : "+l"(d) : "l"(a), "l"(b));
}
__device__ __forceinline__ unsigned long long dup2(float g) {
    unsigned long long v;
    asm("mov.b64 %0, {%1, %1};" : "=l"(v) : "f"(g));
    return v;
}
__device__ __forceinline__ float2 u2f(unsigned long long v) {
    float2 f; asm("mov.b64 {%0,%1}, %2;" : "=f"(f.x), "=f"(f.y) : "l"(v)); return f;
}

// ---------------------------------------------------------------------------
// prep: zero stats, transpose W0/W1 from [O][C][S] to [S*64+C][O]
// ---------------------------------------------------------------------------
__global__ void prep_k(const float* __restrict__ W0, const float* __restrict__ W1) {
    int t = threadIdx.x;
    if (t < 64) { g_sum[t] = 0.f; g_ssq[t] = 0.f; }
    for (int d = t; d < 8192; d += 256) {
        int k = d >> 6, o = d & 63;
        int c = k & 63, s = k >> 6;
        int src = o * 128 + c * 2 + s;
        g_W0t[d] = W0[src];
        g_W1t[d] = W1[src];
    }
}

// ---------------------------------------------------------------------------
// transpose x [B][C][N] -> g_xt [B*N][C]
// ---------------------------------------------------------------------------
__global__ void transpose_k(const float* __restrict__ x) {
    __shared__ float tile[64][33];
    int b = blockIdx.y;
    int n0 = blockIdx.x * 32;
    const float* xb = x + (size_t)b * C_ * N_;
    int t = threadIdx.x;
#pragma unroll
    for (int i = 0; i < 8; i++) {
        int idx = t + i * 256;
        int c = idx >> 5, j = idx & 31;
        tile[c][j] = xb[(size_t)c * N_ + n0 + j];
    }
    __syncthreads();
    float* dst = g_xt + ((size_t)b * N_ + n0) * C_;
#pragma unroll
    for (int i = 0; i < 8; i++) {
        int idx = t + i * 256;
        int j = idx >> 6, c = idx & 63;
        dst[j * C_ + c] = tile[c][j];
    }
}

// ---------------------------------------------------------------------------
// GEMM inner loop: thread = 4 vertices x 8 outputs; f32x2 lanes = output pair.
// G is [128 k][128 v]; Ws is [128 k][64 o].
// ---------------------------------------------------------------------------
__device__ __forceinline__ void gemm_tile(const float* __restrict__ G,
                                          const float* __restrict__ Ws,
                                          int vg, int og,
                                          float av[4][8]) {
    unsigned long long acc[4][4];
#pragma unroll
    for (int v = 0; v < 4; v++)
#pragma unroll
        for (int p = 0; p < 4; p++) acc[v][p] = 0ull;

    const float* Gp = G + 4 * vg;
    const float* Wp = Ws + og * 8;
#pragma unroll 16
    for (int k = 0; k < 128; k++) {
        float4 g4 = *(const float4*)(Gp + (size_t)k * 128);
        ulonglong2 w01 = *(const ulonglong2*)(Wp + (size_t)k * 64);
        ulonglong2 w23 = *(const ulonglong2*)(Wp + (size_t)k * 64 + 4);
        unsigned long long gd0 = dup2(g4.x), gd1 = dup2(g4.y);
        unsigned long long gd2 = dup2(g4.z), gd3 = dup2(g4.w);
        ffma2(acc[0][0], gd0, w01.x); ffma2(acc[0][1], gd0, w01.y);
        ffma2(acc[0][2], gd0, w23.x); ffma2(acc[0][3], gd0, w23.y);
        ffma2(acc[1][0], gd1, w01.x); ffma2(acc[1][1], gd1, w01.y);
        ffma2(acc[1][2], gd1, w23.x); ffma2(acc[1][3], gd1, w23.y);
        ffma2(acc[2][0], gd2, w01.x); ffma2(acc[2][1], gd2, w01.y);
        ffma2(acc[2][2], gd2, w23.x); ffma2(acc[2][3], gd2, w23.y);
        ffma2(acc[3][0], gd3, w01.x); ffma2(acc[3][1], gd3, w01.y);
        ffma2(acc[3][2], gd3, w23.x); ffma2(acc[3][3], gd3, w23.y);
    }
#pragma unroll
    for (int v = 0; v < 4; v++)
#pragma unroll
        for (int p = 0; p < 4; p++) {
            float2 f = u2f(acc[v][p]);
            av[v][2 * p] = f.x;
            av[v][2 * p + 1] = f.y;
        }
}

// ---------------------------------------------------------------------------
// conv1: gather (center + 6-neighbor sum) -> G[128][128]; FFMA2 GEMM;
// store h; accumulate relu stats.
// ---------------------------------------------------------------------------
__global__ __launch_bounds__(256, 2) void conv1_k(const int* __restrict__ neigh) {
    extern __shared__ float smem[];
    float* Ws = smem;           // 128*64  (32 KB)
    float* G  = smem + 8192;    // 128*128 (64 KB)

    int b   = blockIdx.y;
    int n0  = blockIdx.x * TILE_V;
    int tid = threadIdx.x;
    int rbase = b * N_;

    {   // stage weights (32 KB)
        const float4* src = (const float4*)g_W0t;
        float4* dst = (float4*)Ws;
        for (int i = tid; i < 2048; i += 256) dst[i] = src[i];
    }

    {   // gather phase: thread = (vertex v, channel-half)
        int v = tid >> 1, half = tid & 1;
        int n = n0 + v;
        bool ok = (n < N_);
        const float4* xt4 = (const float4*)g_xt;
        size_t nr[6];
        if (ok) {
            const int* nb = neigh + (size_t)(rbase + n) * K_;
#pragma unroll
            for (int k = 0; k < 6; k++) nr[k] = (size_t)(rbase + nb[k]) * 16 + half * 8;
        }
        size_t crow = (size_t)(rbase + n) * 16 + half * 8;
        float4 cen[8], sm[8];
#pragma unroll
        for (int j = 0; j < 8; j++) {
            cen[j] = make_float4(0.f, 0.f, 0.f, 0.f);
            sm[j]  = make_float4(0.f, 0.f, 0.f, 0.f);
        }
        if (ok) {
#pragma unroll
            for (int j = 0; j < 8; j++) cen[j] = xt4[crow + j];
#pragma unroll
            for (int k = 0; k < 6; k++) {
#pragma unroll
                for (int j = 0; j < 8; j++) {
                    float4 a = xt4[nr[k] + j];
                    sm[j].x += a.x; sm[j].y += a.y; sm[j].z += a.z; sm[j].w += a.w;
                }
            }
        }
        int cb = half * 32;
#pragma unroll
        for (int j = 0; j < 8; j++) {
            int c = cb + j * 4;
            G[(c + 0) * 128 + v] = cen[j].x;
            G[(c + 1) * 128 + v] = cen[j].y;
            G[(c + 2) * 128 + v] = cen[j].z;
            G[(c + 3) * 128 + v] = cen[j].w;
            G[(64 + c + 0) * 128 + v] = sm[j].x;
            G[(64 + c + 1) * 128 + v] = sm[j].y;
            G[(64 + c + 2) * 128 + v] = sm[j].z;
            G[(64 + c + 3) * 128 + v] = sm[j].w;
        }
    }
    __syncthreads();

    int vg = tid & 31, og = tid >> 5;   // og == warp id
    float av[4][8];
    gemm_tile(G, Ws, vg, og, av);

    float4* h4 = (float4*)g_h;
#pragma unroll
    for (int i = 0; i < 4; i++) {
        int n = n0 + 4 * vg + i;
        if (n < N_) {
            size_t row = (size_t)(rbase + n) * 16 + og * 2;
            h4[row]     = make_float4(av[i][0], av[i][1], av[i][2], av[i][3]);
            h4[row + 1] = make_float4(av[i][4], av[i][5], av[i][6], av[i][7]);
        }
    }

    // relu stats: warp og owns channels og*8..og*8+7 over all 128 tile vertices
#pragma unroll
    for (int o = 0; o < 8; o++) {
        float s = 0.f, q = 0.f;
#pragma unroll
        for (int i = 0; i < 4; i++) {
            float r = fmaxf(av[i][o], 0.f);
            s += r; q += r * r;
        }
#pragma unroll
        for (int off = 16; off; off >>= 1) {
            s += __shfl_xor_sync(0xffffffffu, s, off);
            q += __shfl_xor_sync(0xffffffffu, q, off);
        }
        if (vg == 0) {
            atomicAdd(&g_sum[og * 8 + o], s);
            atomicAdd(&g_ssq[og * 8 + o], q);
        }
    }
}

// ---------------------------------------------------------------------------
// BN finalize: fold stats + gamma/beta into per-channel affine (a, b)
// ---------------------------------------------------------------------------
__global__ void finalize_k(const float* __restrict__ gamma, const float* __restrict__ beta) {
    int c = threadIdx.x;
    float inv = 1.f / (float)BN_;
    float mean = g_sum[c] * inv;
    float var  = g_ssq[c] * inv - mean * mean;
    float a = gamma[c] * rsqrtf(var + EPS_);
    g_a[c]  = a;
    g_bc[c] = beta[c] - mean * a;
}

// ---------------------------------------------------------------------------
// conv2: gather raw h with BN-affine folding; FFMA2 GEMM; +residual; relu;
// transposed float4 output stores.
// ---------------------------------------------------------------------------
__global__ __launch_bounds__(256, 2) void conv2_k(const int* __restrict__ neigh,
                                                  float* __restrict__ out) {
    extern __shared__ float smem[];
    float* Ws = smem;
    float* G  = smem + 8192;

    int b   = blockIdx.y;
    int n0  = blockIdx.x * TILE_V;
    int tid = threadIdx.x;
    int rbase = b * N_;

    {
        const float4* src = (const float4*)g_W1t;
        float4* dst = (float4*)Ws;
        for (int i = tid; i < 2048; i += 256) dst[i] = src[i];
    }

    {   // gather: center a*relu(h)+b ; neighbors a*sum(relu(h_k)) + 6b
        int v = tid >> 1, half = tid & 1;
        int n = n0 + v;
        bool ok = (n < N_);
        const float4* h4 = (const float4*)g_h;
        const float4* a4 = (const float4*)g_a;
        const float4* b4 = (const float4*)g_bc;
        size_t nr[6];
        if (ok) {
            const int* nb = neigh + (size_t)(rbase + n) * K_;
#pragma unroll
            for (int k = 0; k < 6; k++) nr[k] = (size_t)(rbase + nb[k]) * 16 + half * 8;
        }
        size_t crow = (size_t)(rbase + n) * 16 + half * 8;
        float4 cen[8], sm[8];
#pragma unroll
        for (int j = 0; j < 8; j++) {
            cen[j] = make_float4(0.f, 0.f, 0.f, 0.f);
            sm[j]  = make_float4(0.f, 0.f, 0.f, 0.f);
        }
        if (ok) {
#pragma unroll
            for (int j = 0; j < 8; j++) cen[j] = h4[crow + j];
#pragma unroll
            for (int k = 0; k < 6; k++) {
#pragma unroll
                for (int j = 0; j < 8; j++) {
                    float4 a = h4[nr[k] + j];
                    sm[j].x += fmaxf(a.x, 0.f); sm[j].y += fmaxf(a.y, 0.f);
                    sm[j].z += fmaxf(a.z, 0.f); sm[j].w += fmaxf(a.w, 0.f);
                }
            }
        }
        int cb = half * 32;
#pragma unroll
        for (int j = 0; j < 8; j++) {
            int c = cb + j * 4;
            float4 aa = a4[(half * 8) + j];
            float4 bb = b4[(half * 8) + j];
            G[(c + 0) * 128 + v] = aa.x * fmaxf(cen[j].x, 0.f) + bb.x;
            G[(c + 1) * 128 + v] = aa.y * fmaxf(cen[j].y, 0.f) + bb.y;
            G[(c + 2) * 128 + v] = aa.z * fmaxf(cen[j].z, 0.f) + bb.z;
            G[(c + 3) * 128 + v] = aa.w * fmaxf(cen[j].w, 0.f) + bb.w;
            G[(64 + c + 0) * 128 + v] = aa.x * sm[j].x + 6.f * bb.x;
            G[(64 + c + 1) * 128 + v] = aa.y * sm[j].y + 6.f * bb.y;
            G[(64 + c + 2) * 128 + v] = aa.z * sm[j].z + 6.f * bb.z;
            G[(64 + c + 3) * 128 + v] = aa.w * sm[j].w + 6.f * bb.w;
        }
    }
    __syncthreads();

    int vg = tid & 31, og = tid >> 5;
    float av[4][8];
    gemm_tile(G, Ws, vg, og, av);

    // residual + relu, then transposed float4 stores (4 consecutive vertices)
    int nq = n0 + 4 * vg;
    if (nq < N_) {
        const float4* h4 = (const float4*)g_h;
#pragma unroll
        for (int i = 0; i < 4; i++) {
            size_t row = (size_t)(rbase + nq + i) * 16 + og * 2;
            float4 r0 = h4[row], r1 = h4[row + 1];
            av[i][0] = fmaxf(av[i][0] + r0.x, 0.f);
            av[i][1] = fmaxf(av[i][1] + r0.y, 0.f);
            av[i][2] = fmaxf(av[i][2] + r0.z, 0.f);
            av[i][3] = fmaxf(av[i][3] + r0.w, 0.f);
            av[i][4] = fmaxf(av[i][4] + r1.x, 0.f);
            av[i][5] = fmaxf(av[i][5] + r1.y, 0.f);
            av[i][6] = fmaxf(av[i][6] + r1.z, 0.f);
            av[i][7] = fmaxf(av[i][7] + r1.w, 0.f);
        }
#pragma unroll
        for (int o = 0; o < 8; o++) {
            float4 v4 = make_float4(av[0][o], av[1][o], av[2][o], av[3][o]);
            *(float4*)(out + (size_t)(b * 64 + og * 8 + o) * N_ + nq) = v4;
        }
    }
}

// ---------------------------------------------------------------------------
extern "C" void kernel_launch(void* const* d_in, const int* in_sizes, int n_in,
                              void* d_out, int out_size) {
    const float* x     = (const float*)d_in[0];
    const int*   neigh = (const int*)d_in[1];
    const float* W0    = (const float*)d_in[2];
    const float* W1    = (const float*)d_in[3];
    const float* gamma = (const float*)d_in[4];
    const float* beta  = (const float*)d_in[5];
    float* out = (float*)d_out;

    cudaFuncSetAttribute(conv1_k, cudaFuncAttributeMaxDynamicSharedMemorySize, SMEM_BYTES);
    cudaFuncSetAttribute(conv2_k, cudaFuncAttributeMaxDynamicSharedMemorySize, SMEM_BYTES);

    dim3 gtr(N_ / 32, B_);
    dim3 gconv(NTILES, B_);
    prep_k<<<1, 256>>>(W0, W1);
    transpose_k<<<gtr, 256>>>(x);
    conv1_k<<<gconv, 256, SMEM_BYTES>>>(neigh);
    finalize_k<<<1, 64>>>(gamma, beta);
    conv2_k<<<gconv, 256, SMEM_BYTES>>>(neigh, out);
}